// round 16
// baseline (speedup 1.0000x reference)
#include <cuda_runtime.h>
#include <cuda_fp16.h>
#include <math.h>
#include <stdint.h>

// ---------------------------------------------------------------------------
// Problem constants
// ---------------------------------------------------------------------------
#define DIMM   1024
#define INNER  512
#define BK_CH  256
#define NH     8
#define MQ     (BK_CH*64)       // 16384
#define MKV    (BK_CH*256)      // 65536
#define NX     (4*4096)

// ---------------------------------------------------------------------------
// Scratch
// ---------------------------------------------------------------------------
__device__ __half g_Qh[(size_t)MQ * INNER];
__device__ __half g_Kh[(size_t)MKV * INNER];
__device__ __half g_Vh[(size_t)MKV * INNER];
__device__ __half g_O[(size_t)MQ * INNER];
__device__ __half g_xh[(size_t)NX * DIMM];
__device__ __half g_ch[(size_t)MKV * DIMM];
__device__ __half g_wq[(size_t)DIMM * INNER];
__device__ __half g_wk[(size_t)DIMM * INNER];
__device__ __half g_wv[(size_t)DIMM * INNER];
__device__ __half g_wo[(size_t)INNER * DIMM];
__device__ float  g_kcos[128 * 64];
__device__ float  g_ksin[128 * 64];

// ---------------------------------------------------------------------------
// helpers
// ---------------------------------------------------------------------------
__device__ __forceinline__ uint32_t smem_u32(const void* p) {
    uint32_t a;
    asm("{ .reg .u64 t; cvta.to.shared.u64 t, %1; cvt.u32.u64 %0, t; }" : "=r"(a) : "l"(p));
    return a;
}
__device__ __forceinline__ void mma_f16(float* c, const unsigned* a, const unsigned* b) {
    asm volatile(
        "mma.sync.aligned.m16n8k16.row.col.f32.f16.f16.f32 "
        "{%0,%1,%2,%3}, {%4,%5,%6,%7}, {%8,%9}, {%0,%1,%2,%3};\n"
        : "+f"(c[0]), "+f"(c[1]), "+f"(c[2]), "+f"(c[3])
        : "r"(a[0]), "r"(a[1]), "r"(a[2]), "r"(a[3]),
          "r"(b[0]), "r"(b[1]));
}
__device__ __forceinline__ void ldsm_x4(unsigned& r0, unsigned& r1,
                                        unsigned& r2, unsigned& r3, uint32_t a) {
    asm volatile("ldmatrix.sync.aligned.m8n8.x4.shared.b16 {%0,%1,%2,%3}, [%4];"
                 : "=r"(r0), "=r"(r1), "=r"(r2), "=r"(r3) : "r"(a));
}
__device__ __forceinline__ void ldsm_x4t(unsigned& r0, unsigned& r1,
                                         unsigned& r2, unsigned& r3, uint32_t a) {
    asm volatile("ldmatrix.sync.aligned.m8n8.x4.trans.shared.b16 {%0,%1,%2,%3}, [%4];"
                 : "=r"(r0), "=r"(r1), "=r"(r2), "=r"(r3) : "r"(a));
}
__device__ __forceinline__ void cpa16(uint32_t dst, const void* src, uint32_t ssize) {
    asm volatile("cp.async.cg.shared.global [%0], [%1], 16, %2;"
                 :: "r"(dst), "l"(src), "r"(ssize) : "memory");
}
#define CPA_COMMIT() asm volatile("cp.async.commit_group;" ::: "memory")
#define CPA_WAIT1()  asm volatile("cp.async.wait_group 1;" ::: "memory")

// ---------------------------------------------------------------------------
// Conversions + RoPE preprocessing (unchanged from round 11)
// ---------------------------------------------------------------------------
__global__ void cvt_f16_dual(const float4* __restrict__ in1, uint2* __restrict__ out1, int n1,
                             const float4* __restrict__ in2, uint2* __restrict__ out2, int n2)
{
    int i = blockIdx.x * blockDim.x + threadIdx.x;
    if (i < n1) {
        float4 v = in1[i];
        __half2 a = __floats2half2_rn(v.x, v.y);
        __half2 b = __floats2half2_rn(v.z, v.w);
        out1[i] = make_uint2(*(unsigned*)&a, *(unsigned*)&b);
    } else if (i - n1 < n2) {
        int j = i - n1;
        float4 v = in2[j];
        __half2 a = __floats2half2_rn(v.x, v.y);
        __half2 b = __floats2half2_rn(v.z, v.w);
        out2[j] = make_uint2(*(unsigned*)&a, *(unsigned*)&b);
    }
}

__global__ void rope_tab_kernel(const float* __restrict__ kpe,
                                float* __restrict__ kc, float* __restrict__ ks)
{
    int i = blockIdx.x * 256 + threadIdx.x;
    if (i < 128 * 64) { float f = kpe[i]; kc[i] = cosf(f); ks[i] = sinf(f); }
}

__global__ void rope_k_kernel(__half* __restrict__ Kh,
                              const float* __restrict__ kc, const float* __restrict__ ks)
{
    size_t idx = (size_t)blockIdx.x * 256 + threadIdx.x;
    int d = (int)(idx & 31);
    int h = (int)((idx >> 5) & 7);
    size_t row = idx >> 8;
    int kr = (int)(row & 127);
    size_t base = row * INNER + h * 64;
    float k1 = __half2float(Kh[base + d]);
    float k2 = __half2float(Kh[base + d + 32]);
    float c1 = kc[kr * 64 + d],      s1 = ks[kr * 64 + d];
    float c2 = kc[kr * 64 + d + 32], s2 = ks[kr * 64 + d + 32];
    Kh[base + d]      = __float2half(k1 * c1 - k2 * s1);
    Kh[base + d + 32] = __float2half(k2 * c2 + k1 * s2);
}

__global__ void rope_q_kernel(__half* __restrict__ Qh, const float* __restrict__ qpe63)
{
    int idx = blockIdx.x * 256 + threadIdx.x;
    int d = idx & 31;
    int h = (idx >> 5) & 7;
    int c = idx >> 8;
    size_t base = (size_t)(c * 64) * INNER + h * 64;
    float q1 = __half2float(Qh[base + d]);
    float q2 = __half2float(Qh[base + d + 32]);
    float f1 = qpe63[d], f2 = qpe63[d + 32];
    Qh[base + d]      = __float2half(q1 * cosf(f1) - q2 * sinf(f1));
    Qh[base + d + 32] = __float2half(q2 * cosf(f2) + q1 * sinf(f2));
}

// ---------------------------------------------------------------------------
// FP16 GEMM v5: BM=128, BN=128, BK=64; 256 threads (8 warps 2x4),
// warp tile 64x32, 3 cp.async stages, 2 CTAs/SM. Barrier cadence halved
// vs round-11 (one wait+2 syncs per 64 HMMAs/warp).
// A smem [m][k] stride 72 halves; B smem [k][n] stride 136 halves.
// ---------------------------------------------------------------------------
#define FG_STAGES 3
#define A_STR_H  72
#define B_STR_H  136
#define A_STAGE_B (128 * A_STR_H * 2)           // 18432
#define B_STAGE_B (64 * B_STR_H * 2)            // 17408
#define STAGE_B   (A_STAGE_B + B_STAGE_B)       // 35840
#define FG_SMEM   (FG_STAGES * STAGE_B)         // 107520

template<int GATHER, int EPI, int OUTH>
__global__ __launch_bounds__(256, 2)
void f16_gemm(const __half* __restrict__ A, const __half* __restrict__ W,
              void* __restrict__ Cv, int M, int N, int K,
              const float* __restrict__ bias, float alpha)
{
    extern __shared__ char smc[];
    const uint32_t sbase = smem_u32(smc);

    const int n0 = blockIdx.x * 128;
    const int m0 = blockIdx.y * 128;
    const int t  = threadIdx.x;
    const int lane = t & 31;
    const int warp = t >> 5;
    const int m_base = (warp >> 2) * 64;
    const int n_base = (warp & 3) * 32;
    const int lg = lane >> 2;
    const int lk = lane & 3;
    const int kt = K / 64;

    // A loader: row = t>>1, 4 cpa16 covering 32 halves at off (t&1)*32
    const int arow = t >> 1;
    const int aoff = (t & 1) * 32;               // halves
    const __half* Aptr; uint32_t asz = 16;
    {
        int gm = m0 + arow;
        if (GATHER == 1) {
            int pos = gm & 4095;
            if (pos < 4033) Aptr = A + (size_t)(gm + 63) * K;
            else { Aptr = A; asz = 0; }
        } else Aptr = A + (size_t)gm * K;
    }
    // B loader: row kr = t>>2 (64 rows), 4 cpa16 covering 32 halves at (t&3)*32
    const int bkr  = t >> 2;
    const int boff = (t & 3) * 32;               // halves
    const __half* Wptr = W + (size_t)bkr * N + n0 + boff;

    auto load_stage = [&](int i) {
        const int buf = i % FG_STAGES;
        const int k0  = i * 64;
        const uint32_t ab = sbase + buf * STAGE_B;
        const uint32_t arb = ab + arow * (A_STR_H * 2) + aoff * 2;
        cpa16(arb,      Aptr + k0 + aoff,      asz);
        cpa16(arb + 16, Aptr + k0 + aoff + 8,  asz);
        cpa16(arb + 32, Aptr + k0 + aoff + 16, asz);
        cpa16(arb + 48, Aptr + k0 + aoff + 24, asz);
        const uint32_t bb = ab + A_STAGE_B + bkr * (B_STR_H * 2) + boff * 2;
        cpa16(bb,      Wptr + (size_t)k0 * N,      16);
        cpa16(bb + 16, Wptr + (size_t)k0 * N + 8,  16);
        cpa16(bb + 32, Wptr + (size_t)k0 * N + 16, 16);
        cpa16(bb + 48, Wptr + (size_t)k0 * N + 24, 16);
    };

    float acc[4][4][4];
    #pragma unroll
    for (int i = 0; i < 4; i++)
        #pragma unroll
        for (int j = 0; j < 4; j++)
            #pragma unroll
            for (int q = 0; q < 4; q++) acc[i][j][q] = 0.f;

    #pragma unroll
    for (int s = 0; s < FG_STAGES - 1; s++) { load_stage(s); CPA_COMMIT(); }

    const int a_lrow = lane & 15;
    const int a_lkof = (lane >> 4) << 3;

    for (int i = 0; i < kt; i++) {
        CPA_WAIT1();
        __syncthreads();
        if (i + FG_STAGES - 1 < kt) load_stage(i + FG_STAGES - 1);
        CPA_COMMIT();

        const uint32_t ab = sbase + (i % FG_STAGES) * STAGE_B;
        const uint32_t bb = ab + A_STAGE_B;

        #pragma unroll
        for (int kk0 = 0; kk0 < 64; kk0 += 16) {
            unsigned afr[4][4], bfr[4][2];
            #pragma unroll
            for (int ii = 0; ii < 4; ii++) {
                const uint32_t addr = ab
                    + (m_base + ii * 16 + a_lrow) * (A_STR_H * 2)
                    + (kk0 + a_lkof) * 2;
                ldsm_x4(afr[ii][0], afr[ii][1], afr[ii][2], afr[ii][3], addr);
            }
            #pragma unroll
            for (int jt2 = 0; jt2 < 2; jt2++) {
                const uint32_t addr = bb
                    + (kk0 + a_lrow) * (B_STR_H * 2)
                    + (n_base + jt2 * 16 + a_lkof) * 2;
                ldsm_x4t(bfr[jt2*2][0], bfr[jt2*2][1],
                         bfr[jt2*2+1][0], bfr[jt2*2+1][1], addr);
            }
            #pragma unroll
            for (int ii = 0; ii < 4; ii++)
                #pragma unroll
                for (int j = 0; j < 4; j++)
                    mma_f16(acc[ii][j], afr[ii], bfr[j]);
        }
        __syncthreads();
    }

    #pragma unroll
    for (int i = 0; i < 4; i++) {
        const int r0 = m0 + m_base + i * 16 + lg;
        const int r1 = r0 + 8;
        #pragma unroll
        for (int j = 0; j < 4; j++) {
            const int col = n0 + n_base + j * 8 + (lk << 1);
            if (OUTH == 1) {
                __half* C = (__half*)Cv;
                __half2 p0 = __floats2half2_rn(acc[i][j][0] * alpha, acc[i][j][1] * alpha);
                __half2 p1 = __floats2half2_rn(acc[i][j][2] * alpha, acc[i][j][3] * alpha);
                *(unsigned*)(C + (size_t)r0 * N + col) = *(unsigned*)&p0;
                *(unsigned*)(C + (size_t)r1 * N + col) = *(unsigned*)&p1;
            } else if (EPI == 0) {
                float* C = (float*)Cv;
                *(float2*)(C + (size_t)r0 * N + col) = make_float2(acc[i][j][0], acc[i][j][1]);
                *(float2*)(C + (size_t)r1 * N + col) = make_float2(acc[i][j][2], acc[i][j][3]);
            } else {
                float* C = (float*)Cv;
                const float2 bvv = *(const float2*)(bias + col);
                int pos0 = r0 & 4095;
                if (pos0 < 4033) {
                    const int bb2 = r0 >> 12;
                    float* p = C + ((size_t)bb2 * 4096 + pos0 + 63) * N + col;
                    *(float2*)p = make_float2(acc[i][j][0] + bvv.x, acc[i][j][1] + bvv.y);
                }
                int pos1 = r1 & 4095;
                if (pos1 < 4033) {
                    const int bb2 = r1 >> 12;
                    float* p = C + ((size_t)bb2 * 4096 + pos1 + 63) * N + col;
                    *(float2*)p = make_float2(acc[i][j][2] + bvv.x, acc[i][j][3] + bvv.y);
                }
            }
        }
    }
}

// ---------------------------------------------------------------------------
// Tensor-core attention (unchanged from round 11)
// ---------------------------------------------------------------------------
#define AT_Q_OFF  0
#define AT_KV_OFF 4608
#define AT_S_OFF  13824
#define AT_P_OFF  47616
#define AT_SMEM   68608

__global__ __launch_bounds__(256)
void attn_kernel(const __half* __restrict__ Qh, const __half* __restrict__ Kh,
                 const __half* __restrict__ Vh,
                 const float* __restrict__ null_k,
                 const float* __restrict__ null_v,
                 __half* __restrict__ O)
{
    extern __shared__ char smc[];
    __half* qsm = (__half*)(smc + AT_Q_OFF);
    __half* kvm = (__half*)(smc + AT_KV_OFF);
    float*  S   = (float*) (smc + AT_S_OFF);
    __half* P   = (__half*)(smc + AT_P_OFF);
    const uint32_t qb = smem_u32(qsm);
    const uint32_t kb = smem_u32(kvm);
    const uint32_t pb = smem_u32(P);

    const int c    = blockIdx.x;
    const int h    = blockIdx.y;
    const int r0   = blockIdx.z * 32;
    const int t    = threadIdx.x;
    const int lane = t & 31;
    const int warp = t >> 5;
    const int wm = warp >> 2;
    const int wn = warp & 3;
    const int lg = lane >> 2, lk = lane & 3;
    const int lr = lane & 15, lo = (lane >> 4) << 3;

    {
        int e = t;
        int i = e >> 3, c8 = (e & 7) * 8;
        uint4 v = *(const uint4*)(Qh + ((size_t)(c * 64 + r0 + i)) * INNER + h * 64 + c8);
        *(uint4*)(qsm + i * 72 + c8) = v;
    }
    __syncthreads();

    for (int jt = 0; jt < 5; jt++) {
        for (int e = t; e < 512; e += 256) {
            int jj = e & 63, d0 = (e >> 6) * 8;
            int j = jt * 64 + jj;
            __half v8[8];
            if (j == 0) {
                #pragma unroll
                for (int i = 0; i < 8; i++) v8[i] = __float2half(null_k[h * 64 + d0 + i]);
            } else if (j < 257) {
                uint4 v = *(const uint4*)(Kh + ((size_t)(c * 256 + j - 1)) * INNER + h * 64 + d0);
                *(uint4*)v8 = v;
            } else {
                #pragma unroll
                for (int i = 0; i < 8; i++) v8[i] = __float2half(0.f);
            }
            #pragma unroll
            for (int i = 0; i < 8; i++) kvm[(d0 + i) * 72 + jj] = v8[i];
        }
        __syncthreads();

        float acc[2][4];
        #pragma unroll
        for (int nj = 0; nj < 2; nj++)
            #pragma unroll
            for (int q = 0; q < 4; q++) acc[nj][q] = 0.f;

        #pragma unroll
        for (int kk = 0; kk < 4; kk++) {
            unsigned a[4], b[4];
            ldsm_x4(a[0], a[1], a[2], a[3],
                    qb + (wm * 16 + lr) * 144 + (kk * 16 + lo) * 2);
            ldsm_x4t(b[0], b[1], b[2], b[3],
                     kb + (kk * 16 + lr) * 144 + (wn * 16 + lo) * 2);
            mma_f16(acc[0], a, b);
            mma_f16(acc[1], a, b + 2);
        }
        #pragma unroll
        for (int nj = 0; nj < 2; nj++) {
            int cs = jt * 64 + wn * 16 + nj * 8 + lk * 2;
            if (cs < 263) {
                S[(wm * 16 + lg) * 264 + cs]     = acc[nj][0];
                S[(wm * 16 + lg) * 264 + cs + 1] = acc[nj][1];
                S[(wm * 16 + lg + 8) * 264 + cs]     = acc[nj][2];
                S[(wm * 16 + lg + 8) * 264 + cs + 1] = acc[nj][3];
            }
        }
        __syncthreads();
    }

    for (int r = warp; r < 32; r += 8) {
        float v[9], mx = -1e30f;
        #pragma unroll
        for (int q = 0; q < 9; q++) {
            int j = lane + 32 * q;
            v[q] = (j < 257) ? S[r * 264 + j] : -1e30f;
            mx = fmaxf(mx, v[q]);
        }
        #pragma unroll
        for (int o = 16; o; o >>= 1) mx = fmaxf(mx, __shfl_xor_sync(~0u, mx, o));
        float sum = 0.f;
        #pragma unroll
        for (int q = 0; q < 9; q++) {
            int j = lane + 32 * q;
            v[q] = (j < 257) ? __expf(v[q] - mx) : 0.f;
            sum += v[q];
        }
        #pragma unroll
        for (int o = 16; o; o >>= 1) sum += __shfl_xor_sync(~0u, sum, o);
        float inv = 1.f / sum;
        #pragma unroll
        for (int q = 0; q < 9; q++) {
            int j = lane + 32 * q;
            if (j < 257) P[r * 328 + j] = __float2half(v[q] * inv);
        }
        #pragma unroll
        for (int q = 0; q < 3; q++) {
            int j = 257 + lane + 32 * q;
            if (j < 328) P[r * 328 + j] = __float2half(0.f);
        }
    }
    __syncthreads();

    float oacc[2][4];
    #pragma unroll
    for (int nj = 0; nj < 2; nj++)
        #pragma unroll
        for (int q = 0; q < 4; q++) oacc[nj][q] = 0.f;

    for (int jt = 0; jt < 5; jt++) {
        for (int e = t; e < 512; e += 256) {
            int jj = e >> 3, c8 = (e & 7) * 8;
            int j = jt * 64 + jj;
            uint4 v;
            if (j == 0) {
                __half v8[8];
                #pragma unroll
                for (int i = 0; i < 8; i++) v8[i] = __float2half(null_v[h * 64 + c8 + i]);
                v = *(uint4*)v8;
            } else if (j < 257) {
                v = *(const uint4*)(Vh + ((size_t)(c * 256 + j - 1)) * INNER + h * 64 + c8);
            } else {
                v = make_uint4(0, 0, 0, 0);
            }
            *(uint4*)(kvm + jj * 72 + c8) = v;
        }
        __syncthreads();

        #pragma unroll
        for (int kk = 0; kk < 4; kk++) {
            unsigned a[4], b[4];
            ldsm_x4(a[0], a[1], a[2], a[3],
                    pb + (wm * 16 + lr) * 656 + (jt * 64 + kk * 16 + lo) * 2);
            ldsm_x4t(b[0], b[1], b[2], b[3],
                     kb + (kk * 16 + lr) * 144 + (wn * 16 + lo) * 2);
            mma_f16(oacc[0], a, b);
            mma_f16(oacc[1], a, b + 2);
        }
        __syncthreads();
    }

    #pragma unroll
    for (int nj = 0; nj < 2; nj++) {
        int col = h * 64 + wn * 16 + nj * 8 + lk * 2;
        __half2 p0 = __floats2half2_rn(oacc[nj][0], oacc[nj][1]);
        __half2 p1 = __floats2half2_rn(oacc[nj][2], oacc[nj][3]);
        *(unsigned*)(O + ((size_t)(c * 64 + r0 + wm * 16 + lg)) * INNER + col)     = *(unsigned*)&p0;
        *(unsigned*)(O + ((size_t)(c * 64 + r0 + wm * 16 + lg + 8)) * INNER + col) = *(unsigned*)&p1;
    }
}

// ---------------------------------------------------------------------------
// Zero the first 63 token rows of each batch
// ---------------------------------------------------------------------------
__global__ void zero_prefix_kernel(float* __restrict__ out)
{
    size_t idx = (size_t)blockIdx.x * 256 + threadIdx.x;
    const size_t total = (size_t)4 * 63 * 1024;
    if (idx < total) {
        size_t b   = idx / (63 * 1024);
        size_t rem = idx % (63 * 1024);
        out[b * (size_t)4096 * 1024 + rem] = 0.f;
    }
}

// ---------------------------------------------------------------------------
// Launch
// ---------------------------------------------------------------------------
extern "C" void kernel_launch(void* const* d_in, const int* in_sizes, int n_in,
                              void* d_out, int out_size)
{
    const float* x        = (const float*)d_in[0];
    const float* context  = (const float*)d_in[1];
    const float* q_pos    = (const float*)d_in[2];
    const float* k_pos    = (const float*)d_in[3];
    const float* Wq       = (const float*)d_in[4];
    const float* Wk       = (const float*)d_in[5];
    const float* Wv       = (const float*)d_in[6];
    const float* Wo       = (const float*)d_in[7];
    const float* bo       = (const float*)d_in[8];
    const float* null_k   = (const float*)d_in[9];
    const float* null_v   = (const float*)d_in[10];
    float* out            = (float*)d_out;

    __half *Qh, *Kh, *Vh, *Ob, *Xh, *Ch, *Wqh, *Wkh, *Wvh, *Woh;
    float *Kc, *Ks;
    cudaGetSymbolAddress((void**)&Qh,  g_Qh);
    cudaGetSymbolAddress((void**)&Kh,  g_Kh);
    cudaGetSymbolAddress((void**)&Vh,  g_Vh);
    cudaGetSymbolAddress((void**)&Ob,  g_O);
    cudaGetSymbolAddress((void**)&Xh,  g_xh);
    cudaGetSymbolAddress((void**)&Ch,  g_ch);
    cudaGetSymbolAddress((void**)&Wqh, g_wq);
    cudaGetSymbolAddress((void**)&Wkh, g_wk);
    cudaGetSymbolAddress((void**)&Wvh, g_wv);
    cudaGetSymbolAddress((void**)&Woh, g_wo);
    cudaGetSymbolAddress((void**)&Kc,  g_kcos);
    cudaGetSymbolAddress((void**)&Ks,  g_ksin);

    cudaFuncSetAttribute(f16_gemm<1,0,1>, cudaFuncAttributeMaxDynamicSharedMemorySize, FG_SMEM);
    cudaFuncSetAttribute(f16_gemm<0,0,1>, cudaFuncAttributeMaxDynamicSharedMemorySize, FG_SMEM);
    cudaFuncSetAttribute(f16_gemm<0,1,0>, cudaFuncAttributeMaxDynamicSharedMemorySize, FG_SMEM);
    cudaFuncSetAttribute(attn_kernel,     cudaFuncAttributeMaxDynamicSharedMemorySize, AT_SMEM);

    // conversions + rope tables
    {
        int nw = (DIMM * INNER) / 4;
        cvt_f16_dual<<<(2*nw + 255) / 256, 256>>>(
            (const float4*)Wq, (uint2*)Wqh, nw, (const float4*)Wk, (uint2*)Wkh, nw);
        cvt_f16_dual<<<(2*nw + 255) / 256, 256>>>(
            (const float4*)Wv, (uint2*)Wvh, nw, (const float4*)Wo, (uint2*)Woh, nw);
        int nx4 = (NX * DIMM) / 4;
        int nc4 = (int)(((size_t)MKV * DIMM) / 4);
        cvt_f16_dual<<<(nx4 + nc4 + 255) / 256, 256>>>(
            (const float4*)x, (uint2*)Xh, nx4, (const float4*)context, (uint2*)Ch, nc4);
        rope_tab_kernel<<<32, 256>>>(k_pos, Kc, Ks);
    }

    // Q = shifted-x @ Wq * 0.125 (fp16 out), then rope row-0 per chunk
    {
        dim3 grid(INNER / 128, MQ / 128);
        f16_gemm<1, 0, 1><<<grid, 256, FG_SMEM>>>(Xh, Wqh, Qh, MQ, INNER, DIMM, nullptr, 0.125f);
        rope_q_kernel<<<256, 256>>>(Qh, q_pos + 63 * 64);
    }
    // K = context @ Wk (fp16) + rope; V = context @ Wv (fp16)
    {
        dim3 grid(INNER / 128, MKV / 128);
        f16_gemm<0, 0, 1><<<grid, 256, FG_SMEM>>>(Ch, Wkh, Kh, MKV, INNER, DIMM, nullptr, 1.f);
        rope_k_kernel<<<65536, 256>>>(Kh, Kc, Ks);
        f16_gemm<0, 0, 1><<<grid, 256, FG_SMEM>>>(Ch, Wvh, Vh, MKV, INNER, DIMM, nullptr, 1.f);
    }
    // attention (tensor core)
    {
        dim3 grid(BK_CH, NH, 2);
        attn_kernel<<<grid, 256, AT_SMEM>>>(Qh, Kh, Vh, null_k, null_v, Ob);
    }
    // out = attn_out @ Wo + bo, scattered with +63 shift
    {
        dim3 grid(DIMM / 128, MQ / 128);
        f16_gemm<0, 1, 0><<<grid, 256, FG_SMEM>>>(Ob, Woh, out, MQ, DIMM, INNER, bo, 1.f);
    }
    // zero first 63 rows per batch
    {
        const int total = 4 * 63 * 1024;
        zero_prefix_kernel<<<(total + 255) / 256, 256>>>(out);
    }
}

// round 17
// speedup vs baseline: 1.1477x; 1.1477x over previous
#include <cuda_runtime.h>
#include <cuda_fp16.h>
#include <math.h>
#include <stdint.h>

// ---------------------------------------------------------------------------
// Problem constants
// ---------------------------------------------------------------------------
#define DIMM   1024
#define INNER  512
#define BK_CH  256
#define NH     8
#define MQ     (BK_CH*64)       // 16384
#define MKV    (BK_CH*256)      // 65536
#define NX     (4*4096)

// ---------------------------------------------------------------------------
// Scratch
// ---------------------------------------------------------------------------
__device__ __half g_Qh[(size_t)MQ * INNER];
__device__ __half g_Kh[(size_t)MKV * INNER];
__device__ __half g_Vh[(size_t)MKV * INNER];
__device__ __half g_O[(size_t)MQ * INNER];
__device__ __half g_xh[(size_t)NX * DIMM];
__device__ __half g_ch[(size_t)MKV * DIMM];
__device__ __half g_wq[(size_t)DIMM * INNER];
__device__ __half g_wk[(size_t)DIMM * INNER];
__device__ __half g_wv[(size_t)DIMM * INNER];
__device__ __half g_wo[(size_t)INNER * DIMM];
__device__ float  g_kcos[128 * 64];
__device__ float  g_ksin[128 * 64];

// ---------------------------------------------------------------------------
// helpers
// ---------------------------------------------------------------------------
__device__ __forceinline__ uint32_t smem_u32(const void* p) {
    uint32_t a;
    asm("{ .reg .u64 t; cvta.to.shared.u64 t, %1; cvt.u32.u64 %0, t; }" : "=r"(a) : "l"(p));
    return a;
}
__device__ __forceinline__ void mma_f16(float* c, const unsigned* a, const unsigned* b) {
    asm volatile(
        "mma.sync.aligned.m16n8k16.row.col.f32.f16.f16.f32 "
        "{%0,%1,%2,%3}, {%4,%5,%6,%7}, {%8,%9}, {%0,%1,%2,%3};\n"
        : "+f"(c[0]), "+f"(c[1]), "+f"(c[2]), "+f"(c[3])
        : "r"(a[0]), "r"(a[1]), "r"(a[2]), "r"(a[3]),
          "r"(b[0]), "r"(b[1]));
}
__device__ __forceinline__ void ldsm_x4(unsigned& r0, unsigned& r1,
                                        unsigned& r2, unsigned& r3, uint32_t a) {
    asm volatile("ldmatrix.sync.aligned.m8n8.x4.shared.b16 {%0,%1,%2,%3}, [%4];"
                 : "=r"(r0), "=r"(r1), "=r"(r2), "=r"(r3) : "r"(a));
}
__device__ __forceinline__ void ldsm_x4t(unsigned& r0, unsigned& r1,
                                         unsigned& r2, unsigned& r3, uint32_t a) {
    asm volatile("ldmatrix.sync.aligned.m8n8.x4.trans.shared.b16 {%0,%1,%2,%3}, [%4];"
                 : "=r"(r0), "=r"(r1), "=r"(r2), "=r"(r3) : "r"(a));
}
__device__ __forceinline__ void cpa16(uint32_t dst, const void* src, uint32_t ssize) {
    asm volatile("cp.async.cg.shared.global [%0], [%1], 16, %2;"
                 :: "r"(dst), "l"(src), "r"(ssize) : "memory");
}
#define CPA_COMMIT() asm volatile("cp.async.commit_group;" ::: "memory")
#define CPA_WAIT2()  asm volatile("cp.async.wait_group 2;" ::: "memory")

// ---------------------------------------------------------------------------
// Conversions + RoPE preprocessing (unchanged from round 11)
// ---------------------------------------------------------------------------
__global__ void cvt_f16_dual(const float4* __restrict__ in1, uint2* __restrict__ out1, int n1,
                             const float4* __restrict__ in2, uint2* __restrict__ out2, int n2)
{
    int i = blockIdx.x * blockDim.x + threadIdx.x;
    if (i < n1) {
        float4 v = in1[i];
        __half2 a = __floats2half2_rn(v.x, v.y);
        __half2 b = __floats2half2_rn(v.z, v.w);
        out1[i] = make_uint2(*(unsigned*)&a, *(unsigned*)&b);
    } else if (i - n1 < n2) {
        int j = i - n1;
        float4 v = in2[j];
        __half2 a = __floats2half2_rn(v.x, v.y);
        __half2 b = __floats2half2_rn(v.z, v.w);
        out2[j] = make_uint2(*(unsigned*)&a, *(unsigned*)&b);
    }
}

__global__ void rope_tab_kernel(const float* __restrict__ kpe,
                                float* __restrict__ kc, float* __restrict__ ks)
{
    int i = blockIdx.x * 256 + threadIdx.x;
    if (i < 128 * 64) { float f = kpe[i]; kc[i] = cosf(f); ks[i] = sinf(f); }
}

__global__ void rope_k_kernel(__half* __restrict__ Kh,
                              const float* __restrict__ kc, const float* __restrict__ ks)
{
    size_t idx = (size_t)blockIdx.x * 256 + threadIdx.x;
    int d = (int)(idx & 31);
    int h = (int)((idx >> 5) & 7);
    size_t row = idx >> 8;
    int kr = (int)(row & 127);
    size_t base = row * INNER + h * 64;
    float k1 = __half2float(Kh[base + d]);
    float k2 = __half2float(Kh[base + d + 32]);
    float c1 = kc[kr * 64 + d],      s1 = ks[kr * 64 + d];
    float c2 = kc[kr * 64 + d + 32], s2 = ks[kr * 64 + d + 32];
    Kh[base + d]      = __float2half(k1 * c1 - k2 * s1);
    Kh[base + d + 32] = __float2half(k2 * c2 + k1 * s2);
}

__global__ void rope_q_kernel(__half* __restrict__ Qh, const float* __restrict__ qpe63)
{
    int idx = blockIdx.x * 256 + threadIdx.x;
    int d = idx & 31;
    int h = (idx >> 5) & 7;
    int c = idx >> 8;
    size_t base = (size_t)(c * 64) * INNER + h * 64;
    float q1 = __half2float(Qh[base + d]);
    float q2 = __half2float(Qh[base + d + 32]);
    float f1 = qpe63[d], f2 = qpe63[d + 32];
    Qh[base + d]      = __float2half(q1 * cosf(f1) - q2 * sinf(f1));
    Qh[base + d + 32] = __float2half(q2 * cosf(f2) + q1 * sinf(f2));
}

// ---------------------------------------------------------------------------
// FP16 GEMM (exact round-11 config: BM=128, BN=128, BK=32, 256 thr, 4 stages)
// ---------------------------------------------------------------------------
#define FG_STAGES 4
#define A_STR_H  40
#define B_STR_H  136
#define A_STAGE_B (128 * A_STR_H * 2)
#define B_STAGE_B (32 * B_STR_H * 2)
#define STAGE_B   (A_STAGE_B + B_STAGE_B)
#define FG_SMEM   (FG_STAGES * STAGE_B)

template<int GATHER, int EPI, int OUTH>
__global__ __launch_bounds__(256, 2)
void f16_gemm(const __half* __restrict__ A, const __half* __restrict__ W,
              void* __restrict__ Cv, int M, int N, int K,
              const float* __restrict__ bias, float alpha)
{
    extern __shared__ char smc[];
    const uint32_t sbase = smem_u32(smc);

    const int n0 = blockIdx.x * 128;
    const int m0 = blockIdx.y * 128;
    const int t  = threadIdx.x;
    const int lane = t & 31;
    const int warp = t >> 5;
    const int m_base = (warp >> 2) * 64;
    const int n_base = (warp & 3) * 32;
    const int lg = lane >> 2;
    const int lk = lane & 3;
    const int kt = K / 32;

    const int arow = t >> 1;
    const int aoff = (t & 1) * 16;
    const __half* Aptr; uint32_t asz = 16;
    {
        int gm = m0 + arow;
        if (GATHER == 1) {
            int pos = gm & 4095;
            if (pos < 4033) Aptr = A + (size_t)(gm + 63) * K;
            else { Aptr = A; asz = 0; }
        } else Aptr = A + (size_t)gm * K;
    }
    const int bkr  = t >> 3;
    const int boff = (t & 7) * 16;
    const __half* Wptr = W + (size_t)bkr * N + n0 + boff;

    auto load_stage = [&](int i) {
        const int buf = i % FG_STAGES;
        const int k0  = i * 32;
        const uint32_t ab = sbase + buf * STAGE_B;
        cpa16(ab + arow * (A_STR_H * 2) + aoff * 2,      Aptr + k0 + aoff,     asz);
        cpa16(ab + arow * (A_STR_H * 2) + aoff * 2 + 16, Aptr + k0 + aoff + 8, asz);
        const uint32_t bb = ab + A_STAGE_B;
        cpa16(bb + bkr * (B_STR_H * 2) + boff * 2,      Wptr + (size_t)k0 * N,     16);
        cpa16(bb + bkr * (B_STR_H * 2) + boff * 2 + 16, Wptr + (size_t)k0 * N + 8, 16);
    };

    float acc[4][4][4];
    #pragma unroll
    for (int i = 0; i < 4; i++)
        #pragma unroll
        for (int j = 0; j < 4; j++)
            #pragma unroll
            for (int q = 0; q < 4; q++) acc[i][j][q] = 0.f;

    #pragma unroll
    for (int s = 0; s < FG_STAGES - 1; s++) { load_stage(s); CPA_COMMIT(); }

    const int a_lrow = lane & 15;
    const int a_lkof = (lane >> 4) << 3;

    for (int i = 0; i < kt; i++) {
        CPA_WAIT2();
        __syncthreads();
        if (i + FG_STAGES - 1 < kt) load_stage(i + FG_STAGES - 1);
        CPA_COMMIT();

        const uint32_t ab = sbase + (i % FG_STAGES) * STAGE_B;
        const uint32_t bb = ab + A_STAGE_B;

        #pragma unroll
        for (int kk0 = 0; kk0 < 32; kk0 += 16) {
            unsigned afr[4][4], bfr[4][2];
            #pragma unroll
            for (int ii = 0; ii < 4; ii++) {
                const uint32_t addr = ab
                    + (m_base + ii * 16 + a_lrow) * (A_STR_H * 2)
                    + (kk0 + a_lkof) * 2;
                ldsm_x4(afr[ii][0], afr[ii][1], afr[ii][2], afr[ii][3], addr);
            }
            #pragma unroll
            for (int jt2 = 0; jt2 < 2; jt2++) {
                const uint32_t addr = bb
                    + (kk0 + a_lrow) * (B_STR_H * 2)
                    + (n_base + jt2 * 16 + a_lkof) * 2;
                ldsm_x4t(bfr[jt2*2][0], bfr[jt2*2][1],
                         bfr[jt2*2+1][0], bfr[jt2*2+1][1], addr);
            }
            #pragma unroll
            for (int ii = 0; ii < 4; ii++)
                #pragma unroll
                for (int j = 0; j < 4; j++)
                    mma_f16(acc[ii][j], afr[ii], bfr[j]);
        }
        __syncthreads();
    }

    #pragma unroll
    for (int i = 0; i < 4; i++) {
        const int r0 = m0 + m_base + i * 16 + lg;
        const int r1 = r0 + 8;
        #pragma unroll
        for (int j = 0; j < 4; j++) {
            const int col = n0 + n_base + j * 8 + (lk << 1);
            if (OUTH == 1) {
                __half* C = (__half*)Cv;
                __half2 p0 = __floats2half2_rn(acc[i][j][0] * alpha, acc[i][j][1] * alpha);
                __half2 p1 = __floats2half2_rn(acc[i][j][2] * alpha, acc[i][j][3] * alpha);
                *(unsigned*)(C + (size_t)r0 * N + col) = *(unsigned*)&p0;
                *(unsigned*)(C + (size_t)r1 * N + col) = *(unsigned*)&p1;
            } else if (EPI == 0) {
                float* C = (float*)Cv;
                *(float2*)(C + (size_t)r0 * N + col) = make_float2(acc[i][j][0], acc[i][j][1]);
                *(float2*)(C + (size_t)r1 * N + col) = make_float2(acc[i][j][2], acc[i][j][3]);
            } else {
                float* C = (float*)Cv;
                const float2 bvv = *(const float2*)(bias + col);
                int pos0 = r0 & 4095;
                if (pos0 < 4033) {
                    const int bb2 = r0 >> 12;
                    float* p = C + ((size_t)bb2 * 4096 + pos0 + 63) * N + col;
                    *(float2*)p = make_float2(acc[i][j][0] + bvv.x, acc[i][j][1] + bvv.y);
                }
                int pos1 = r1 & 4095;
                if (pos1 < 4033) {
                    const int bb2 = r1 >> 12;
                    float* p = C + ((size_t)bb2 * 4096 + pos1 + 63) * N + col;
                    *(float2*)p = make_float2(acc[i][j][2] + bvv.x, acc[i][j][3] + bvv.y);
                }
            }
        }
    }
}

// ---------------------------------------------------------------------------
// Tensor-core attention v2: K tile stored naturally [kv][d] (vectorized),
// QK^T B-fragments via non-trans ldsm_x4 on [n][k] (mirror identity of
// ldsm_x4t on [k][n]); fragment pairing {r0,r2} / {r1,r3}.
// ---------------------------------------------------------------------------
#define AT_Q_OFF  0
#define AT_KV_OFF 4608
#define AT_S_OFF  13824
#define AT_P_OFF  47616
#define AT_SMEM   68608

__global__ __launch_bounds__(256)
void attn_kernel(const __half* __restrict__ Qh, const __half* __restrict__ Kh,
                 const __half* __restrict__ Vh,
                 const float* __restrict__ null_k,
                 const float* __restrict__ null_v,
                 __half* __restrict__ O)
{
    extern __shared__ char smc[];
    __half* qsm = (__half*)(smc + AT_Q_OFF);    // [32][72]
    __half* kvm = (__half*)(smc + AT_KV_OFF);   // [64][72]  (K and V both [kv][d])
    float*  S   = (float*) (smc + AT_S_OFF);    // [32][264]
    __half* P   = (__half*)(smc + AT_P_OFF);    // [32][328]
    const uint32_t qb = smem_u32(qsm);
    const uint32_t kb = smem_u32(kvm);
    const uint32_t pb = smem_u32(P);

    const int c    = blockIdx.x;
    const int h    = blockIdx.y;
    const int r0   = blockIdx.z * 32;
    const int t    = threadIdx.x;
    const int lane = t & 31;
    const int warp = t >> 5;
    const int wm = warp >> 2;
    const int wn = warp & 3;
    const int lg = lane >> 2, lk = lane & 3;
    const int lr = lane & 15, lo = (lane >> 4) << 3;

    // ---- load Q tile ----
    {
        int e = t;
        int i = e >> 3, c8 = (e & 7) * 8;
        uint4 v = *(const uint4*)(Qh + ((size_t)(c * 64 + r0 + i)) * INNER + h * 64 + c8);
        *(uint4*)(qsm + i * 72 + c8) = v;
    }
    __syncthreads();

    // ---- S = Q @ K^T over 5 kv tiles; K stored [kv][d], vectorized ----
    for (int jt = 0; jt < 5; jt++) {
        for (int e = t; e < 512; e += 256) {
            int jj = e >> 3, c8 = (e & 7) * 8;
            int j = jt * 64 + jj;
            uint4 v;
            if (j == 0) {
                __half v8[8];
                #pragma unroll
                for (int i = 0; i < 8; i++) v8[i] = __float2half(null_k[h * 64 + c8 + i]);
                v = *(uint4*)v8;
            } else if (j < 257) {
                v = *(const uint4*)(Kh + ((size_t)(c * 256 + j - 1)) * INNER + h * 64 + c8);
            } else {
                v = make_uint4(0, 0, 0, 0);
            }
            *(uint4*)(kvm + jj * 72 + c8) = v;
        }
        __syncthreads();

        float acc[2][4];
        #pragma unroll
        for (int nj = 0; nj < 2; nj++)
            #pragma unroll
            for (int q = 0; q < 4; q++) acc[nj][q] = 0.f;

        #pragma unroll
        for (int kk = 0; kk < 4; kk++) {
            unsigned a[4], r[4];
            ldsm_x4(a[0], a[1], a[2], a[3],
                    qb + (wm * 16 + lr) * 144 + (kk * 16 + lo) * 2);
            // non-trans ldsm over K's [n][k] rows: n = wn*16 + lr, k = kk*16 + lo
            ldsm_x4(r[0], r[1], r[2], r[3],
                    kb + (wn * 16 + lr) * 144 + (kk * 16 + lo) * 2);
            unsigned b0[2] = { r[0], r[2] };   // n-subtile 0 (cols 0-7)
            unsigned b1[2] = { r[1], r[3] };   // n-subtile 1 (cols 8-15)
            mma_f16(acc[0], a, b0);
            mma_f16(acc[1], a, b1);
        }
        #pragma unroll
        for (int nj = 0; nj < 2; nj++) {
            int cs = jt * 64 + wn * 16 + nj * 8 + lk * 2;
            if (cs < 263) {
                S[(wm * 16 + lg) * 264 + cs]     = acc[nj][0];
                S[(wm * 16 + lg) * 264 + cs + 1] = acc[nj][1];
                S[(wm * 16 + lg + 8) * 264 + cs]     = acc[nj][2];
                S[(wm * 16 + lg + 8) * 264 + cs + 1] = acc[nj][3];
            }
        }
        __syncthreads();
    }

    // ---- softmax (257 cols), P fp16 with cols 257..327 zeroed ----
    for (int r = warp; r < 32; r += 8) {
        float v[9], mx = -1e30f;
        #pragma unroll
        for (int q = 0; q < 9; q++) {
            int j = lane + 32 * q;
            v[q] = (j < 257) ? S[r * 264 + j] : -1e30f;
            mx = fmaxf(mx, v[q]);
        }
        #pragma unroll
        for (int o = 16; o; o >>= 1) mx = fmaxf(mx, __shfl_xor_sync(~0u, mx, o));
        float sum = 0.f;
        #pragma unroll
        for (int q = 0; q < 9; q++) {
            int j = lane + 32 * q;
            v[q] = (j < 257) ? __expf(v[q] - mx) : 0.f;
            sum += v[q];
        }
        #pragma unroll
        for (int o = 16; o; o >>= 1) sum += __shfl_xor_sync(~0u, sum, o);
        float inv = 1.f / sum;
        #pragma unroll
        for (int q = 0; q < 9; q++) {
            int j = lane + 32 * q;
            if (j < 257) P[r * 328 + j] = __float2half(v[q] * inv);
        }
        #pragma unroll
        for (int q = 0; q < 3; q++) {
            int j = 257 + lane + 32 * q;
            if (j < 328) P[r * 328 + j] = __float2half(0.f);
        }
    }
    __syncthreads();

    // ---- O = P @ V over 5 kv tiles (V [kv][d] = [k][n] -> ldsm_x4t) ----
    float oacc[2][4];
    #pragma unroll
    for (int nj = 0; nj < 2; nj++)
        #pragma unroll
        for (int q = 0; q < 4; q++) oacc[nj][q] = 0.f;

    for (int jt = 0; jt < 5; jt++) {
        for (int e = t; e < 512; e += 256) {
            int jj = e >> 3, c8 = (e & 7) * 8;
            int j = jt * 64 + jj;
            uint4 v;
            if (j == 0) {
                __half v8[8];
                #pragma unroll
                for (int i = 0; i < 8; i++) v8[i] = __float2half(null_v[h * 64 + c8 + i]);
                v = *(uint4*)v8;
            } else if (j < 257) {
                v = *(const uint4*)(Vh + ((size_t)(c * 256 + j - 1)) * INNER + h * 64 + c8);
            } else {
                v = make_uint4(0, 0, 0, 0);
            }
            *(uint4*)(kvm + jj * 72 + c8) = v;
        }
        __syncthreads();

        #pragma unroll
        for (int kk = 0; kk < 4; kk++) {
            unsigned a[4], b[4];
            ldsm_x4(a[0], a[1], a[2], a[3],
                    pb + (wm * 16 + lr) * 656 + (jt * 64 + kk * 16 + lo) * 2);
            ldsm_x4t(b[0], b[1], b[2], b[3],
                     kb + (kk * 16 + lr) * 144 + (wn * 16 + lo) * 2);
            mma_f16(oacc[0], a, b);
            mma_f16(oacc[1], a, b + 2);
        }
        __syncthreads();
    }

    #pragma unroll
    for (int nj = 0; nj < 2; nj++) {
        int col = h * 64 + wn * 16 + nj * 8 + lk * 2;
        __half2 p0 = __floats2half2_rn(oacc[nj][0], oacc[nj][1]);
        __half2 p1 = __floats2half2_rn(oacc[nj][2], oacc[nj][3]);
        *(unsigned*)(O + ((size_t)(c * 64 + r0 + wm * 16 + lg)) * INNER + col)     = *(unsigned*)&p0;
        *(unsigned*)(O + ((size_t)(c * 64 + r0 + wm * 16 + lg + 8)) * INNER + col) = *(unsigned*)&p1;
    }
}

// ---------------------------------------------------------------------------
// Zero the first 63 token rows of each batch
// ---------------------------------------------------------------------------
__global__ void zero_prefix_kernel(float* __restrict__ out)
{
    size_t idx = (size_t)blockIdx.x * 256 + threadIdx.x;
    const size_t total = (size_t)4 * 63 * 1024;
    if (idx < total) {
        size_t b   = idx / (63 * 1024);
        size_t rem = idx % (63 * 1024);
        out[b * (size_t)4096 * 1024 + rem] = 0.f;
    }
}

// ---------------------------------------------------------------------------
// Launch
// ---------------------------------------------------------------------------
extern "C" void kernel_launch(void* const* d_in, const int* in_sizes, int n_in,
                              void* d_out, int out_size)
{
    const float* x        = (const float*)d_in[0];
    const float* context  = (const float*)d_in[1];
    const float* q_pos    = (const float*)d_in[2];
    const float* k_pos    = (const float*)d_in[3];
    const float* Wq       = (const float*)d_in[4];
    const float* Wk       = (const float*)d_in[5];
    const float* Wv       = (const float*)d_in[6];
    const float* Wo       = (const float*)d_in[7];
    const float* bo       = (const float*)d_in[8];
    const float* null_k   = (const float*)d_in[9];
    const float* null_v   = (const float*)d_in[10];
    float* out            = (float*)d_out;

    __half *Qh, *Kh, *Vh, *Ob, *Xh, *Ch, *Wqh, *Wkh, *Wvh, *Woh;
    float *Kc, *Ks;
    cudaGetSymbolAddress((void**)&Qh,  g_Qh);
    cudaGetSymbolAddress((void**)&Kh,  g_Kh);
    cudaGetSymbolAddress((void**)&Vh,  g_Vh);
    cudaGetSymbolAddress((void**)&Ob,  g_O);
    cudaGetSymbolAddress((void**)&Xh,  g_xh);
    cudaGetSymbolAddress((void**)&Ch,  g_ch);
    cudaGetSymbolAddress((void**)&Wqh, g_wq);
    cudaGetSymbolAddress((void**)&Wkh, g_wk);
    cudaGetSymbolAddress((void**)&Wvh, g_wv);
    cudaGetSymbolAddress((void**)&Woh, g_wo);
    cudaGetSymbolAddress((void**)&Kc,  g_kcos);
    cudaGetSymbolAddress((void**)&Ks,  g_ksin);

    cudaFuncSetAttribute(f16_gemm<1,0,1>, cudaFuncAttributeMaxDynamicSharedMemorySize, FG_SMEM);
    cudaFuncSetAttribute(f16_gemm<0,0,1>, cudaFuncAttributeMaxDynamicSharedMemorySize, FG_SMEM);
    cudaFuncSetAttribute(f16_gemm<0,1,0>, cudaFuncAttributeMaxDynamicSharedMemorySize, FG_SMEM);
    cudaFuncSetAttribute(attn_kernel,     cudaFuncAttributeMaxDynamicSharedMemorySize, AT_SMEM);

    // conversions + rope tables
    {
        int nw = (DIMM * INNER) / 4;
        cvt_f16_dual<<<(2*nw + 255) / 256, 256>>>(
            (const float4*)Wq, (uint2*)Wqh, nw, (const float4*)Wk, (uint2*)Wkh, nw);
        cvt_f16_dual<<<(2*nw + 255) / 256, 256>>>(
            (const float4*)Wv, (uint2*)Wvh, nw, (const float4*)Wo, (uint2*)Woh, nw);
        int nx4 = (NX * DIMM) / 4;
        int nc4 = (int)(((size_t)MKV * DIMM) / 4);
        cvt_f16_dual<<<(nx4 + nc4 + 255) / 256, 256>>>(
            (const float4*)x, (uint2*)Xh, nx4, (const float4*)context, (uint2*)Ch, nc4);
        rope_tab_kernel<<<32, 256>>>(k_pos, Kc, Ks);
    }

    // Q = shifted-x @ Wq * 0.125 (fp16 out), then rope row-0 per chunk
    {
        dim3 grid(INNER / 128, MQ / 128);
        f16_gemm<1, 0, 1><<<grid, 256, FG_SMEM>>>(Xh, Wqh, Qh, MQ, INNER, DIMM, nullptr, 0.125f);
        rope_q_kernel<<<256, 256>>>(Qh, q_pos + 63 * 64);
    }
    // K = context @ Wk (fp16) + rope; V = context @ Wv (fp16)
    {
        dim3 grid(INNER / 128, MKV / 128);
        f16_gemm<0, 0, 1><<<grid, 256, FG_SMEM>>>(Ch, Wkh, Kh, MKV, INNER, DIMM, nullptr, 1.f);
        rope_k_kernel<<<65536, 256>>>(Kh, Kc, Ks);
        f16_gemm<0, 0, 1><<<grid, 256, FG_SMEM>>>(Ch, Wvh, Vh, MKV, INNER, DIMM, nullptr, 1.f);
    }
    // attention (tensor core)
    {
        dim3 grid(BK_CH, NH, 2);
        attn_kernel<<<grid, 256, AT_SMEM>>>(Qh, Kh, Vh, null_k, null_v, Ob);
    }
    // out = attn_out @ Wo + bo, scattered with +63 shift
    {
        dim3 grid(DIMM / 128, MQ / 128);
        f16_gemm<0, 1, 0><<<grid, 256, FG_SMEM>>>(Ob, Woh, out, MQ, DIMM, INNER, bo, 1.f);
    }
    // zero first 63 rows per batch
    {
        const int total = 4 * 63 * 1024;
        zero_prefix_kernel<<<(total + 255) / 256, 256>>>(out);
    }
}